// round 9
// baseline (speedup 1.0000x reference)
#include <cuda_runtime.h>

// SelfAttn: B=16, C=64, H=W=64. theta/phi: 8 ch, g: 32 ch.
// phi,g maxpooled 2x2 -> M=1024 keys. HW=4096 queries.

#define BATCH 16
#define CDIM  64
#define HWDIM 4096
#define MDIM  1024
#define CT    8
#define CG    32
#define MSPLIT 2
#define MHALF (MDIM / MSPLIT)   // 512

typedef unsigned long long u64;

__device__ __forceinline__ u64 pack2(float lo, float hi) {
    u64 r; asm("mov.b64 %0, {%1,%2};" : "=l"(r) : "f"(lo), "f"(hi)); return r;
}
__device__ __forceinline__ float2 unpack2(u64 v) {
    float2 r; asm("mov.b64 {%0,%1}, %2;" : "=f"(r.x), "=f"(r.y) : "l"(v)); return r;
}
__device__ __forceinline__ u64 ffma2(u64 a, u64 b, u64 c) {
    u64 d; asm("fma.rn.f32x2 %0, %1, %2, %3;" : "=l"(d) : "l"(a), "l"(b), "l"(c)); return d;
}
__device__ __forceinline__ u64 fadd2(u64 a, u64 b) {
    u64 d; asm("add.rn.f32x2 %0, %1, %2;" : "=l"(d) : "l"(a), "l"(b)); return d;
}
__device__ __forceinline__ u64 fmul2(u64 a, u64 b) {
    u64 d; asm("mul.rn.f32x2 %0, %1, %2;" : "=l"(d) : "l"(a), "l"(b)); return d;
}
__device__ __forceinline__ float ex2f(float x) {
    float r; asm("ex2.approx.ftz.f32 %0, %1;" : "=f"(r) : "f"(x)); return r;
}
__device__ __forceinline__ u64 max2(u64 a, u64 b) {
    float2 x = unpack2(a), y = unpack2(b);
    return pack2(fmaxf(x.x, y.x), fmaxf(x.y, y.y));
}

#define LOG2E 1.4426950408889634f

// Scratch (allocation-free rule: __device__ globals)
__device__ float d_theta[BATCH * HWDIM * CT];            // [b][n][8]
__device__ float d_phi  [BATCH * MDIM  * CT];            // [b][m][8]
__device__ float d_gbuf [BATCH * MDIM  * CG];            // [b][m][32]
__device__ float d_part [BATCH * MSPLIT * HWDIM * CG];   // [b][s][n][k]
__device__ float d_psum [BATCH * MSPLIT * HWDIM];        // [b][s][n]

// ---------------------------------------------------------------------------
// Kernel A: 1x1 projections + fused 2x2 maxpool for phi/g.
// TWO horizontal pixels per thread (one pool pair): 12 weight LDS.128 per
// c-iter now feed 48 FFMA2 -> crossbar load halved vs 1px/thread.
// CTA 128 thr = 4 rows (warp w = row w of strip). Horizontal pool max is
// in-thread; vertical via one smem exchange. grid (16, 16).
// ---------------------------------------------------------------------------
__global__ __launch_bounds__(128) void proj_kernel(
    const float* __restrict__ x,
    const float* __restrict__ wt,
    const float* __restrict__ wp,
    const float* __restrict__ wg)
{
    __shared__ __align__(16) u64 s_wt2[CDIM * 4];
    __shared__ __align__(16) u64 s_wp2[CDIM * 4];
    __shared__ __align__(16) u64 s_wg2[CDIM * 16];
    __shared__ __align__(16) u64 s_pool[2][32][20];   // [rowpair][pool col][4+16]
    int tid = threadIdx.x;
    for (int i = tid; i < CDIM * 4; i += 128) {
        int c = i >> 2, j = i & 3;
        s_wt2[i] = pack2(wt[(2 * j) * CDIM + c], wt[(2 * j + 1) * CDIM + c]);
        s_wp2[i] = pack2(wp[(2 * j) * CDIM + c], wp[(2 * j + 1) * CDIM + c]);
    }
    for (int i = tid; i < CDIM * 16; i += 128) {
        int c = i >> 4, j = i & 15;
        s_wg2[i] = pack2(wg[(2 * j) * CDIM + c], wg[(2 * j + 1) * CDIM + c]);
    }
    __syncthreads();

    int b     = blockIdx.y;
    int strip = blockIdx.x;           // 4 rows per strip
    int w     = tid >> 5;             // row within strip (0..3)
    int lane  = tid & 31;
    int row   = strip * 4 + w;
    int p0    = row * 64 + 2 * lane;  // even pixel of the horizontal pair
    const float* xb = x + (size_t)b * CDIM * HWDIM;

    u64 th0[4], th1[4], ph0[4], ph1[4], g0[16], g1[16];
#pragma unroll
    for (int j = 0; j < 4; j++) { th0[j] = th1[j] = ph0[j] = ph1[j] = 0ull; }
#pragma unroll
    for (int j = 0; j < 16; j++) { g0[j] = g1[j] = 0ull; }

#pragma unroll 4
    for (int c = 0; c < CDIM; c++) {
        float2 a = *(const float2*)(xb + (size_t)c * HWDIM + p0);
        u64 xa = pack2(a.x, a.x);
        u64 xc = pack2(a.y, a.y);
        const ulonglong2* wtp = (const ulonglong2*)(s_wt2 + c * 4);
        const ulonglong2* wpp = (const ulonglong2*)(s_wp2 + c * 4);
        const ulonglong2* wgp = (const ulonglong2*)(s_wg2 + c * 16);
#pragma unroll
        for (int jj = 0; jj < 2; jj++) {
            ulonglong2 wv = wtp[jj];
            th0[2 * jj]     = ffma2(wv.x, xa, th0[2 * jj]);
            th1[2 * jj]     = ffma2(wv.x, xc, th1[2 * jj]);
            th0[2 * jj + 1] = ffma2(wv.y, xa, th0[2 * jj + 1]);
            th1[2 * jj + 1] = ffma2(wv.y, xc, th1[2 * jj + 1]);
            ulonglong2 pv = wpp[jj];
            ph0[2 * jj]     = ffma2(pv.x, xa, ph0[2 * jj]);
            ph1[2 * jj]     = ffma2(pv.x, xc, ph1[2 * jj]);
            ph0[2 * jj + 1] = ffma2(pv.y, xa, ph0[2 * jj + 1]);
            ph1[2 * jj + 1] = ffma2(pv.y, xc, ph1[2 * jj + 1]);
        }
#pragma unroll
        for (int jj = 0; jj < 8; jj++) {
            ulonglong2 wv = wgp[jj];
            g0[2 * jj]     = ffma2(wv.x, xa, g0[2 * jj]);
            g1[2 * jj]     = ffma2(wv.x, xc, g1[2 * jj]);
            g0[2 * jj + 1] = ffma2(wv.y, xa, g0[2 * jj + 1]);
            g1[2 * jj + 1] = ffma2(wv.y, xc, g1[2 * jj + 1]);
        }
    }

    // theta stores (4 x STG.128)
    {
        ulonglong2* t0 = (ulonglong2*)&d_theta[((size_t)b * HWDIM + p0) * CT];
        t0[0] = make_ulonglong2(th0[0], th0[1]);
        t0[1] = make_ulonglong2(th0[2], th0[3]);
        ulonglong2* t1 = (ulonglong2*)&d_theta[((size_t)b * HWDIM + p0 + 1) * CT];
        t1[0] = make_ulonglong2(th1[0], th1[1]);
        t1[1] = make_ulonglong2(th1[2], th1[3]);
    }

    // horizontal pool max in-thread
#pragma unroll
    for (int j = 0; j < 4; j++)  ph0[j] = max2(ph0[j], ph1[j]);
#pragma unroll
    for (int j = 0; j < 16; j++) g0[j]  = max2(g0[j],  g1[j]);

    // vertical pool: odd rows (w=1,3) publish; even rows (w=0,2) combine+store
    int rp = w >> 1;
    if (w & 1) {
#pragma unroll
        for (int j = 0; j < 4; j++)  s_pool[rp][lane][j]     = ph0[j];
#pragma unroll
        for (int j = 0; j < 16; j++) s_pool[rp][lane][4 + j] = g0[j];
    }
    __syncthreads();
    if (!(w & 1)) {
        int pp = (strip * 2 + rp) * 32 + lane;
        u64* pph = (u64*)&d_phi[((size_t)b * MDIM + pp) * CT];
#pragma unroll
        for (int j = 0; j < 4; j++)  pph[j] = max2(ph0[j], s_pool[rp][lane][j]);
        u64* pg = (u64*)&d_gbuf[((size_t)b * MDIM + pp) * CG];
#pragma unroll
        for (int j = 0; j < 16; j++) pg[j] = max2(g0[j], s_pool[rp][lane][4 + j]);
    }
}

// ---------------------------------------------------------------------------
// Kernel B: fused attention over half the keys, TWO queries per thread.
// grid (8 qtile, 2 split, 16 batch) = 256 CTAs, 256 threads, smem 80KB ->
// 2 CTAs/SM = 4 warps/SMSP. LDS amortized over 2 queries -> FMA-pipe-bound.
// Partials stored [n][k] -> 4 STG.128 per query instead of 32 STG.32.
// ---------------------------------------------------------------------------
__global__ __launch_bounds__(256, 2) void attn_kernel(void)
{
    extern __shared__ u64 smem[];
    u64* s_phi = smem;                 // [512][4]  pairs of phi channels
    u64* s_g   = smem + MHALF * 4;     // [512][16] pairs of g channels

    int tid = threadIdx.x;
    int qt  = blockIdx.x;
    int sp  = blockIdx.y;
    int b   = blockIdx.z;
    int m0  = sp * MHALF;

    {   // cooperative smem fill (float4)
        const float4* sph = (const float4*)&d_phi[((size_t)b * MDIM + m0) * CT];
        float4* dph = (float4*)s_phi;
        for (int i = tid; i < MHALF * CT / 4; i += 256) dph[i] = sph[i];
        const float4* sg = (const float4*)&d_gbuf[((size_t)b * MDIM + m0) * CG];
        float4* dg = (float4*)s_g;
        for (int i = tid; i < MHALF * CG / 4; i += 256) dg[i] = sg[i];
    }
    __syncthreads();

    int n0 = qt * 512 + tid;
    int n1 = n0 + 256;
    u64 ta[4], tb[4];
    {
        const float4* thp = (const float4*)&d_theta[((size_t)b * HWDIM + n0) * CT];
        float4 t0 = thp[0], t1 = thp[1];
        ta[0] = pack2(t0.x * LOG2E, t0.y * LOG2E);
        ta[1] = pack2(t0.z * LOG2E, t0.w * LOG2E);
        ta[2] = pack2(t1.x * LOG2E, t1.y * LOG2E);
        ta[3] = pack2(t1.z * LOG2E, t1.w * LOG2E);
        const float4* thq = (const float4*)&d_theta[((size_t)b * HWDIM + n1) * CT];
        float4 u0 = thq[0], u1 = thq[1];
        tb[0] = pack2(u0.x * LOG2E, u0.y * LOG2E);
        tb[1] = pack2(u0.z * LOG2E, u0.w * LOG2E);
        tb[2] = pack2(u1.x * LOG2E, u1.y * LOG2E);
        tb[3] = pack2(u1.z * LOG2E, u1.w * LOG2E);
    }
    const u64 s_init = pack2(-12.0f * LOG2E, 0.0f);   // uniform shift, cancels

    float sum0 = 0.0f, sum1 = 0.0f;
    u64 acc0[16], acc1[16];
#pragma unroll
    for (int k = 0; k < 16; k++) { acc0[k] = 0ull; acc1[k] = 0ull; }

#pragma unroll 8
    for (int m = 0; m < MHALF; m++) {
        const ulonglong2* pp = (const ulonglong2*)(s_phi + m * 4);
        ulonglong2 pa = pp[0], pb = pp[1];
        u64 s0 = ffma2(ta[0], pa.x, s_init);
        s0 = ffma2(ta[1], pa.y, s0);
        s0 = ffma2(ta[2], pb.x, s0);
        s0 = ffma2(ta[3], pb.y, s0);
        u64 s1 = ffma2(tb[0], pa.x, s_init);
        s1 = ffma2(tb[1], pa.y, s1);
        s1 = ffma2(tb[2], pb.x, s1);
        s1 = ffma2(tb[3], pb.y, s1);
        float2 v0 = unpack2(s0);
        float2 v1 = unpack2(s1);
        float e0 = ex2f(v0.x + v0.y);
        float e1 = ex2f(v1.x + v1.y);
        sum0 += e0;
        sum1 += e1;
        u64 e02 = pack2(e0, e0);
        u64 e12 = pack2(e1, e1);
        const ulonglong2* gp = (const ulonglong2*)(s_g + m * 16);
#pragma unroll
        for (int q = 0; q < 8; q++) {
            ulonglong2 gv = gp[q];
            acc0[2 * q]     = ffma2(e02, gv.x, acc0[2 * q]);
            acc0[2 * q + 1] = ffma2(e02, gv.y, acc0[2 * q + 1]);
            acc1[2 * q]     = ffma2(e12, gv.x, acc1[2 * q]);
            acc1[2 * q + 1] = ffma2(e12, gv.y, acc1[2 * q + 1]);
        }
    }

    // write unnormalized partials, [b][s][n][k]: 4 STG.128 per query
    {
        ulonglong2* pb0 = (ulonglong2*)&d_part[(((size_t)b * MSPLIT + sp) * HWDIM + n0) * CG];
#pragma unroll
        for (int j = 0; j < 8; j++) pb0[j] = make_ulonglong2(acc0[2 * j], acc0[2 * j + 1]);
        ulonglong2* pb1 = (ulonglong2*)&d_part[(((size_t)b * MSPLIT + sp) * HWDIM + n1) * CG];
#pragma unroll
        for (int j = 0; j < 8; j++) pb1[j] = make_ulonglong2(acc1[2 * j], acc1[2 * j + 1]);
    }
    d_psum[((size_t)b * MSPLIT + sp) * HWDIM + n0] = sum0;
    d_psum[((size_t)b * MSPLIT + sp) * HWDIM + n1] = sum1;
}

// ---------------------------------------------------------------------------
// Kernel C: combine partials, normalize, w_o GEMV, gamma * o + x.
// grid (16, 16), 256 threads. One thread per query. Memory-bound (~66MB).
// ---------------------------------------------------------------------------
__global__ __launch_bounds__(256) void combine_kernel(
    const float* __restrict__ x,
    const float* __restrict__ wo,
    const float* __restrict__ gamma,
    float* __restrict__ out)
{
    __shared__ u64 s_wo2[CDIM * 16];   // pairs over k: {wo[c][2j], wo[c][2j+1]}
    int tid = threadIdx.x;
    for (int i = tid; i < CDIM * 16; i += 256) {
        int c = i >> 4, j = i & 15;
        s_wo2[i] = pack2(wo[c * CG + 2 * j], wo[c * CG + 2 * j + 1]);
    }
    __syncthreads();

    int b = blockIdx.y;
    int n = blockIdx.x * 256 + tid;

    const u64* q0 = (const u64*)&d_part[(((size_t)b * MSPLIT + 0) * HWDIM + n) * CG];
    const u64* q1 = (const u64*)&d_part[(((size_t)b * MSPLIT + 1) * HWDIM + n) * CG];
    float s0 = d_psum[((size_t)b * MSPLIT + 0) * HWDIM + n];
    float s1 = d_psum[((size_t)b * MSPLIT + 1) * HWDIM + n];
    float inv = 1.0f / (s0 + s1);
    u64 inv2 = pack2(inv, inv);

    u64 o2[16];
#pragma unroll
    for (int j = 0; j < 16; j++) o2[j] = fmul2(fadd2(q0[j], q1[j]), inv2);

    float gm = *gamma;
    const float* xb = x   + (size_t)b * CDIM * HWDIM + n;
    float*       ob = out + (size_t)b * CDIM * HWDIM + n;
#pragma unroll
    for (int c = 0; c < CDIM; c++) {
        u64 v2 = 0ull;
#pragma unroll
        for (int j = 0; j < 16; j++) v2 = ffma2(s_wo2[c * 16 + j], o2[j], v2);
        float2 v = unpack2(v2);
        ob[(size_t)c * HWDIM] = fmaf(gm, v.x + v.y, xb[(size_t)c * HWDIM]);
    }
}

// ---------------------------------------------------------------------------
extern "C" void kernel_launch(void* const* d_in, const int* in_sizes, int n_in,
                              void* d_out, int out_size)
{
    const float* x  = (const float*)d_in[0];
    const float* wt = (const float*)d_in[1];
    const float* wp = (const float*)d_in[2];
    const float* wg = (const float*)d_in[3];
    const float* wo = (const float*)d_in[4];
    const float* gm = (const float*)d_in[5];
    float* out = (float*)d_out;

    proj_kernel<<<dim3(16, BATCH), 128>>>(x, wt, wp, wg);

    int smem_bytes = (MHALF * 4 + MHALF * 16) * (int)sizeof(u64);   // 81920
    cudaFuncSetAttribute(attn_kernel, cudaFuncAttributeMaxDynamicSharedMemorySize,
                         smem_bytes);
    attn_kernel<<<dim3(HWDIM / 512, MSPLIT, BATCH), 256, smem_bytes>>>();

    combine_kernel<<<dim3(HWDIM / 256, BATCH), 256>>>(x, wo, gm, out);
}

// round 13
// speedup vs baseline: 1.9086x; 1.9086x over previous
#include <cuda_runtime.h>
#include <cuda_bf16.h>
#include <cstdint>

// SelfAttn: B=16, C=64, H=W=64. theta/phi: 8 ch, g: 32 ch.
// phi,g maxpooled 2x2 -> M=1024 keys. HW=4096 queries.

#define BATCH 16
#define CDIM  64
#define HWDIM 4096
#define MDIM  1024
#define CT    8
#define CG    32

typedef unsigned long long u64;

__device__ __forceinline__ u64 pack2(float lo, float hi) {
    u64 r; asm("mov.b64 %0, {%1,%2};" : "=l"(r) : "f"(lo), "f"(hi)); return r;
}
__device__ __forceinline__ float2 unpack2(u64 v) {
    float2 r; asm("mov.b64 {%0,%1}, %2;" : "=f"(r.x), "=f"(r.y) : "l"(v)); return r;
}
__device__ __forceinline__ u64 ffma2(u64 a, u64 b, u64 c) {
    u64 d; asm("fma.rn.f32x2 %0, %1, %2, %3;" : "=l"(d) : "l"(a), "l"(b), "l"(c)); return d;
}
__device__ __forceinline__ float ex2f(float x) {
    float r; asm("ex2.approx.ftz.f32 %0, %1;" : "=f"(r) : "f"(x)); return r;
}
__device__ __forceinline__ u64 max2(u64 a, u64 b) {
    float2 x = unpack2(a), y = unpack2(b);
    return pack2(fmaxf(x.x, y.x), fmaxf(x.y, y.y));
}
// bf16x2 pack: lower half = lo, upper half = hi
__device__ __forceinline__ uint32_t cvt2(float lo, float hi) {
    uint32_t r; asm("cvt.rn.bf16x2.f32 %0, %1, %2;" : "=r"(r) : "f"(hi), "f"(lo)); return r;
}

#define LOG2E 1.4426950408889634f

// Scratch (allocation-free rule: __device__ globals)
__device__ float d_theta[BATCH * HWDIM * CT];   // [b][n][8]
__device__ float d_phi  [BATCH * MDIM  * CT];   // [b][m][8]
__device__ float d_gbuf [BATCH * CG * MDIM];    // TRANSPOSED: [b][ch][m]

// ---------------------------------------------------------------------------
// Kernel A: 1x1 projections + fused 2x2 maxpool for phi/g.
// One thread per PIXEL. CTA = 128 threads = 2 rows x 64 cols. grid (32, 16).
// g written channel-major [b][ch][m] for the mma attention kernel.
// ---------------------------------------------------------------------------
__global__ __launch_bounds__(128) void proj_kernel(
    const float* __restrict__ x,
    const float* __restrict__ wt,
    const float* __restrict__ wp,
    const float* __restrict__ wg)
{
    __shared__ __align__(16) u64 s_wt2[CDIM * 4];
    __shared__ __align__(16) u64 s_wp2[CDIM * 4];
    __shared__ __align__(16) u64 s_wg2[CDIM * 16];
    __shared__ __align__(16) u64 s_pool[32][20];
    int tid = threadIdx.x;
    for (int i = tid; i < CDIM * 4; i += 128) {
        int c = i >> 2, j = i & 3;
        s_wt2[i] = pack2(wt[(2 * j) * CDIM + c], wt[(2 * j + 1) * CDIM + c]);
        s_wp2[i] = pack2(wp[(2 * j) * CDIM + c], wp[(2 * j + 1) * CDIM + c]);
    }
    for (int i = tid; i < CDIM * 16; i += 128) {
        int c = i >> 4, j = i & 15;
        s_wg2[i] = pack2(wg[(2 * j) * CDIM + c], wg[(2 * j + 1) * CDIM + c]);
    }
    __syncthreads();

    int b   = blockIdx.y;
    int py  = blockIdx.x;
    int row = 2 * py + (tid >> 6);
    int col = tid & 63;
    int pix = row * 64 + col;
    const float* xb = x + (size_t)b * CDIM * HWDIM;

    u64 th[4], ph[4], gg[16];
#pragma unroll
    for (int j = 0; j < 4; j++) { th[j] = 0ull; ph[j] = 0ull; }
#pragma unroll
    for (int j = 0; j < 16; j++) gg[j] = 0ull;

#pragma unroll 8
    for (int c = 0; c < CDIM; c++) {
        float a = xb[(size_t)c * HWDIM + pix];
        u64 x2 = pack2(a, a);
        const ulonglong2* wtp = (const ulonglong2*)(s_wt2 + c * 4);
        const ulonglong2* wpp = (const ulonglong2*)(s_wp2 + c * 4);
        const ulonglong2* wgp = (const ulonglong2*)(s_wg2 + c * 16);
#pragma unroll
        for (int jj = 0; jj < 2; jj++) {
            ulonglong2 w = wtp[jj];
            th[2 * jj]     = ffma2(w.x, x2, th[2 * jj]);
            th[2 * jj + 1] = ffma2(w.y, x2, th[2 * jj + 1]);
            ulonglong2 v = wpp[jj];
            ph[2 * jj]     = ffma2(v.x, x2, ph[2 * jj]);
            ph[2 * jj + 1] = ffma2(v.y, x2, ph[2 * jj + 1]);
        }
#pragma unroll
        for (int jj = 0; jj < 8; jj++) {
            ulonglong2 w = wgp[jj];
            gg[2 * jj]     = ffma2(w.x, x2, gg[2 * jj]);
            gg[2 * jj + 1] = ffma2(w.y, x2, gg[2 * jj + 1]);
        }
    }

    {
        ulonglong2* tp = (ulonglong2*)&d_theta[((size_t)b * HWDIM + pix) * CT];
        tp[0] = make_ulonglong2(th[0], th[1]);
        tp[1] = make_ulonglong2(th[2], th[3]);
    }

#pragma unroll
    for (int j = 0; j < 4; j++)
        ph[j] = max2(ph[j], __shfl_xor_sync(0xffffffffu, ph[j], 1));
#pragma unroll
    for (int j = 0; j < 16; j++)
        gg[j] = max2(gg[j], __shfl_xor_sync(0xffffffffu, gg[j], 1));

    bool evencol = !(col & 1);
    int pc = col >> 1;
    if (tid >= 64 && evencol) {
#pragma unroll
        for (int j = 0; j < 4; j++)  s_pool[pc][j]     = ph[j];
#pragma unroll
        for (int j = 0; j < 16; j++) s_pool[pc][4 + j] = gg[j];
    }
    __syncthreads();
    if (tid < 64 && evencol) {
        int pp = py * 32 + pc;
        u64* pph = (u64*)&d_phi[((size_t)b * MDIM + pp) * CT];
#pragma unroll
        for (int j = 0; j < 4; j++)  pph[j] = max2(ph[j], s_pool[pc][j]);
#pragma unroll
        for (int j = 0; j < 16; j++) {
            float2 v = unpack2(max2(gg[j], s_pool[pc][4 + j]));
            d_gbuf[((size_t)b * CG + 2 * j)     * MDIM + pp] = v.x;
            d_gbuf[((size_t)b * CG + 2 * j + 1) * MDIM + pp] = v.y;
        }
    }
}

// ---------------------------------------------------------------------------
// Kernel B: mma.sync (bf16 HMMA) fused attention.
// CTA = 256 queries x all 1024 keys, 256 thr (8 warps x 32 q), grid (16,16).
// Scores fp32 scalar -> bf16 A-fragments in registers (no P smem).
// G bf16 in smem [40][1048] (32 ch + ones row 32 -> sum = D col 32).
// D accumulated fp32 in registers; epilogue reuses G smem as o-buffer, then
// w_o GEMV + residual in-CTA.
// ---------------------------------------------------------------------------
#define PHIP   12                         // fp32 per phi row (pad: conflict-free)
#define GPITCH 1048                       // bf16 per gT row (pad: conflict-free)
#define OBP    34                         // fp32 per o_buf row
#define OFF_PHI 0
#define OFF_GT  (MDIM * PHIP * 4)                 // 49152
#define OFF_WO  (OFF_GT + 40 * GPITCH * 2)        // 132992
#define SMEM_SZ (OFF_WO + CDIM * 16 * 8)          // 141184

__device__ __forceinline__ void mma16816(float* c, const uint32_t* a,
                                         uint32_t b0, uint32_t b1) {
    asm volatile(
        "mma.sync.aligned.m16n8k16.row.col.f32.bf16.bf16.f32 "
        "{%0,%1,%2,%3}, {%4,%5,%6,%7}, {%8,%9}, {%0,%1,%2,%3};"
        : "+f"(c[0]), "+f"(c[1]), "+f"(c[2]), "+f"(c[3])
        : "r"(a[0]), "r"(a[1]), "r"(a[2]), "r"(a[3]), "r"(b0), "r"(b1));
}

__global__ __launch_bounds__(256) void attn_mma_kernel(
    const float* __restrict__ x,
    const float* __restrict__ wo,
    const float* __restrict__ gamma,
    float* __restrict__ out)
{
    extern __shared__ __align__(16) char smem[];
    float* s_phi = (float*)(smem + OFF_PHI);
    char*  s_gt  = smem + OFF_GT;
    u64*   s_wo2 = (u64*)(smem + OFF_WO);

    int tid  = threadIdx.x;
    int lane = tid & 31, wid = tid >> 5;
    int qt   = blockIdx.x, b = blockIdx.y;

    // --- fills ---
    for (int i = tid; i < MDIM * 2; i += 256) {
        int row = i >> 1, h = i & 1;
        *(float4*)(s_phi + row * PHIP + h * 4) =
            *(const float4*)(d_phi + ((size_t)b * MDIM + row) * CT + h * 4);
    }
    for (int i = tid; i < 32 * 128; i += 256) {
        int r = i >> 7, seg = i & 127;
        const float4* gs = (const float4*)(d_gbuf + ((size_t)b * CG + r) * MDIM + seg * 8);
        float4 A = gs[0], C = gs[1];
        __nv_bfloat162 h0 = __floats2bfloat162_rn(A.x, A.y);
        __nv_bfloat162 h1 = __floats2bfloat162_rn(A.z, A.w);
        __nv_bfloat162 h2 = __floats2bfloat162_rn(C.x, C.y);
        __nv_bfloat162 h3 = __floats2bfloat162_rn(C.z, C.w);
        uint4 w = make_uint4(*(uint32_t*)&h0, *(uint32_t*)&h1,
                             *(uint32_t*)&h2, *(uint32_t*)&h3);
        *(uint4*)(s_gt + r * (GPITCH * 2) + seg * 16) = w;
    }
    // rows 32..39: ones row (sum) + zeros
    for (int rr = 32; rr < 40; rr++) {
        for (int i = tid; i < 131; i += 256) {
            uint4 w = make_uint4(0, 0, 0, 0);
            if (rr == 32 && i * 8 < 1024)
                w = make_uint4(0x3F803F80u, 0x3F803F80u, 0x3F803F80u, 0x3F803F80u);
            *(uint4*)(s_gt + rr * (GPITCH * 2) + i * 16) = w;
        }
    }
    for (int i = tid; i < CDIM * 16; i += 256) {
        int c = i >> 4, j = i & 15;
        s_wo2[i] = pack2(wo[c * CG + 2 * j], wo[c * CG + 2 * j + 1]);
    }
    __syncthreads();

    // --- theta in registers (4 rows x 8 floats, scaled by log2e) ---
    int r  = lane >> 2;
    int qw = qt * 256 + wid * 32;
    u64 th[4][4];
#pragma unroll
    for (int i = 0; i < 4; i++) {
        const float4* tp = (const float4*)(d_theta + ((size_t)b * HWDIM + qw + r + i * 8) * CT);
        float4 t0 = tp[0], t1 = tp[1];
        th[i][0] = pack2(t0.x * LOG2E, t0.y * LOG2E);
        th[i][1] = pack2(t0.z * LOG2E, t0.w * LOG2E);
        th[i][2] = pack2(t1.x * LOG2E, t1.y * LOG2E);
        th[i][3] = pack2(t1.z * LOG2E, t1.w * LOG2E);
    }
    const u64 s_init = pack2(-12.0f * LOG2E, 0.0f);   // uniform shift, cancels

    float acc[2][5][4];
#pragma unroll
    for (int t = 0; t < 2; t++)
#pragma unroll
        for (int nc = 0; nc < 5; nc++)
#pragma unroll
            for (int j = 0; j < 4; j++) acc[t][nc][j] = 0.0f;

    // --- main loop: 64 chunks of 16 keys ---
    for (int k0 = 0; k0 < MDIM; k0 += 16) {
        int kc = k0 + 2 * (lane & 3);
        // phi rows kc, kc+1, kc+8, kc+9
        u64 ph[4][4];
#pragma unroll
        for (int kk = 0; kk < 4; kk++) {
            int krow = kc + (kk & 1) + (kk >> 1) * 8;
            const float4* pp = (const float4*)(s_phi + krow * PHIP);
            float4 p0 = pp[0], p1 = pp[1];
            ph[kk][0] = pack2(p0.x, p0.y); ph[kk][1] = pack2(p0.z, p0.w);
            ph[kk][2] = pack2(p1.x, p1.y); ph[kk][3] = pack2(p1.z, p1.w);
        }
        // 16 scores (4 theta rows x 4 keys) in fp32, then exp
        float e[4][4];
#pragma unroll
        for (int i = 0; i < 4; i++)
#pragma unroll
            for (int kk = 0; kk < 4; kk++) {
                u64 s = ffma2(th[i][0], ph[kk][0], s_init);
                s = ffma2(th[i][1], ph[kk][1], s);
                s = ffma2(th[i][2], ph[kk][2], s);
                s = ffma2(th[i][3], ph[kk][3], s);
                float2 v = unpack2(s);
                e[i][kk] = ex2f(v.x + v.y);
            }
        // A fragments (bf16x2): m-tile t uses theta rows 2t, 2t+1
        uint32_t a[2][4];
#pragma unroll
        for (int t = 0; t < 2; t++) {
            a[t][0] = cvt2(e[2 * t][0],     e[2 * t][1]);
            a[t][1] = cvt2(e[2 * t + 1][0], e[2 * t + 1][1]);
            a[t][2] = cvt2(e[2 * t][2],     e[2 * t][3]);
            a[t][3] = cvt2(e[2 * t + 1][2], e[2 * t + 1][3]);
        }
        // B fragments + MMA
        uint32_t koff = (uint32_t)(k0 + 2 * (lane & 3)) * 2;
#pragma unroll
        for (int nc = 0; nc < 5; nc++) {
            const char* brow = s_gt + (nc * 8 + r) * (GPITCH * 2) + koff;
            uint32_t b0 = *(const uint32_t*)brow;
            uint32_t b1 = *(const uint32_t*)(brow + 16);
            mma16816(acc[0][nc], a[0], b0, b1);
            mma16816(acc[1][nc], a[1], b0, b1);
        }
    }

    // --- epilogue: normalize, stage o, GEMV, residual ---
    __syncthreads();                     // gT no longer needed
    float* o_buf = (float*)(smem + OFF_GT);
    int src = lane & ~3;
#pragma unroll
    for (int t = 0; t < 2; t++) {
        float inv0 = 1.0f / __shfl_sync(0xffffffffu, acc[t][4][0], src);
        float inv1 = 1.0f / __shfl_sync(0xffffffffu, acc[t][4][2], src);
        int q0 = wid * 32 + t * 16 + r;
        int q1 = q0 + 8;
#pragma unroll
        for (int nc = 0; nc < 4; nc++) {
            int col = nc * 8 + 2 * (lane & 3);
            *(float2*)(o_buf + q0 * OBP + col) =
                make_float2(acc[t][nc][0] * inv0, acc[t][nc][1] * inv0);
            *(float2*)(o_buf + q1 * OBP + col) =
                make_float2(acc[t][nc][2] * inv1, acc[t][nc][3] * inv1);
        }
    }
    __syncthreads();

    u64 o2[16];
#pragma unroll
    for (int j = 0; j < 16; j++) {
        float2 v = *(float2*)(o_buf + tid * OBP + 2 * j);
        o2[j] = pack2(v.x, v.y);
    }
    float gm = *gamma;
    int n = qt * 256 + tid;
    const float* xb = x   + (size_t)b * CDIM * HWDIM + n;
    float*       ob = out + (size_t)b * CDIM * HWDIM + n;
#pragma unroll 4
    for (int c = 0; c < CDIM; c++) {
        const ulonglong2* wr = (const ulonglong2*)(s_wo2 + c * 16);
        u64 v2 = 0ull;
#pragma unroll
        for (int j = 0; j < 8; j++) {
            ulonglong2 w = wr[j];
            v2 = ffma2(w.x, o2[2 * j],     v2);
            v2 = ffma2(w.y, o2[2 * j + 1], v2);
        }
        float2 v = unpack2(v2);
        ob[(size_t)c * HWDIM] = fmaf(gm, v.x + v.y, xb[(size_t)c * HWDIM]);
    }
}

// ---------------------------------------------------------------------------
extern "C" void kernel_launch(void* const* d_in, const int* in_sizes, int n_in,
                              void* d_out, int out_size)
{
    const float* x  = (const float*)d_in[0];
    const float* wt = (const float*)d_in[1];
    const float* wp = (const float*)d_in[2];
    const float* wg = (const float*)d_in[3];
    const float* wo = (const float*)d_in[4];
    const float* gm = (const float*)d_in[5];
    float* out = (float*)d_out;

    proj_kernel<<<dim3(32, BATCH), 128>>>(x, wt, wp, wg);

    cudaFuncSetAttribute(attn_mma_kernel, cudaFuncAttributeMaxDynamicSharedMemorySize, SMEM_SZ);
    attn_mma_kernel<<<dim3(HWDIM / 256, BATCH), 256, SMEM_SZ>>>(x, wo, gm, out);
}

// round 14
// speedup vs baseline: 2.0443x; 1.0711x over previous
#include <cuda_runtime.h>
#include <cuda_bf16.h>
#include <cstdint>

// SelfAttn: B=16, C=64, H=W=64. theta/phi: 8 ch, g: 32 ch.
// phi,g maxpooled 2x2 -> M=1024 keys. HW=4096 queries.

#define BATCH 16
#define CDIM  64
#define HWDIM 4096
#define MDIM  1024
#define CT    8
#define CG    32

typedef unsigned long long u64;

__device__ __forceinline__ u64 pack2(float lo, float hi) {
    u64 r; asm("mov.b64 %0, {%1,%2};" : "=l"(r) : "f"(lo), "f"(hi)); return r;
}
__device__ __forceinline__ float2 unpack2(u64 v) {
    float2 r; asm("mov.b64 {%0,%1}, %2;" : "=f"(r.x), "=f"(r.y) : "l"(v)); return r;
}
__device__ __forceinline__ u64 ffma2(u64 a, u64 b, u64 c) {
    u64 d; asm("fma.rn.f32x2 %0, %1, %2, %3;" : "=l"(d) : "l"(a), "l"(b), "l"(c)); return d;
}
__device__ __forceinline__ float ex2f(float x) {
    float r; asm("ex2.approx.ftz.f32 %0, %1;" : "=f"(r) : "f"(x)); return r;
}
__device__ __forceinline__ u64 max2(u64 a, u64 b) {
    float2 x = unpack2(a), y = unpack2(b);
    return pack2(fmaxf(x.x, y.x), fmaxf(x.y, y.y));
}
// bf16x2 pack: lower half = lo, upper half = hi
__device__ __forceinline__ uint32_t cvt2(float lo, float hi) {
    uint32_t r; asm("cvt.rn.bf16x2.f32 %0, %1, %2;" : "=r"(r) : "f"(hi), "f"(lo)); return r;
}

#define LOG2E 1.4426950408889634f

// Scratch (allocation-free rule: __device__ globals)
__device__ float d_theta[BATCH * HWDIM * CT];   // [b][n][8]
__device__ float d_phi  [BATCH * MDIM  * CT];   // [b][m][8]
__device__ float d_gbuf [BATCH * CG * MDIM];    // TRANSPOSED: [b][ch][m]

// ---------------------------------------------------------------------------
// Kernel A: 1x1 projections + fused 2x2 maxpool for phi/g.
// One thread per PIXEL. CTA = 128 threads = 2 rows x 64 cols. grid (32, 16).
// ---------------------------------------------------------------------------
__global__ __launch_bounds__(128) void proj_kernel(
    const float* __restrict__ x,
    const float* __restrict__ wt,
    const float* __restrict__ wp,
    const float* __restrict__ wg)
{
    __shared__ __align__(16) u64 s_wt2[CDIM * 4];
    __shared__ __align__(16) u64 s_wp2[CDIM * 4];
    __shared__ __align__(16) u64 s_wg2[CDIM * 16];
    __shared__ __align__(16) u64 s_pool[32][20];
    int tid = threadIdx.x;
    for (int i = tid; i < CDIM * 4; i += 128) {
        int c = i >> 2, j = i & 3;
        s_wt2[i] = pack2(wt[(2 * j) * CDIM + c], wt[(2 * j + 1) * CDIM + c]);
        s_wp2[i] = pack2(wp[(2 * j) * CDIM + c], wp[(2 * j + 1) * CDIM + c]);
    }
    for (int i = tid; i < CDIM * 16; i += 128) {
        int c = i >> 4, j = i & 15;
        s_wg2[i] = pack2(wg[(2 * j) * CDIM + c], wg[(2 * j + 1) * CDIM + c]);
    }
    __syncthreads();

    int b   = blockIdx.y;
    int py  = blockIdx.x;
    int row = 2 * py + (tid >> 6);
    int col = tid & 63;
    int pix = row * 64 + col;
    const float* xb = x + (size_t)b * CDIM * HWDIM;

    u64 th[4], ph[4], gg[16];
#pragma unroll
    for (int j = 0; j < 4; j++) { th[j] = 0ull; ph[j] = 0ull; }
#pragma unroll
    for (int j = 0; j < 16; j++) gg[j] = 0ull;

#pragma unroll 8
    for (int c = 0; c < CDIM; c++) {
        float a = xb[(size_t)c * HWDIM + pix];
        u64 x2 = pack2(a, a);
        const ulonglong2* wtp = (const ulonglong2*)(s_wt2 + c * 4);
        const ulonglong2* wpp = (const ulonglong2*)(s_wp2 + c * 4);
        const ulonglong2* wgp = (const ulonglong2*)(s_wg2 + c * 16);
#pragma unroll
        for (int jj = 0; jj < 2; jj++) {
            ulonglong2 w = wtp[jj];
            th[2 * jj]     = ffma2(w.x, x2, th[2 * jj]);
            th[2 * jj + 1] = ffma2(w.y, x2, th[2 * jj + 1]);
            ulonglong2 v = wpp[jj];
            ph[2 * jj]     = ffma2(v.x, x2, ph[2 * jj]);
            ph[2 * jj + 1] = ffma2(v.y, x2, ph[2 * jj + 1]);
        }
#pragma unroll
        for (int jj = 0; jj < 8; jj++) {
            ulonglong2 w = wgp[jj];
            gg[2 * jj]     = ffma2(w.x, x2, gg[2 * jj]);
            gg[2 * jj + 1] = ffma2(w.y, x2, gg[2 * jj + 1]);
        }
    }

    {
        ulonglong2* tp = (ulonglong2*)&d_theta[((size_t)b * HWDIM + pix) * CT];
        tp[0] = make_ulonglong2(th[0], th[1]);
        tp[1] = make_ulonglong2(th[2], th[3]);
    }

#pragma unroll
    for (int j = 0; j < 4; j++)
        ph[j] = max2(ph[j], __shfl_xor_sync(0xffffffffu, ph[j], 1));
#pragma unroll
    for (int j = 0; j < 16; j++)
        gg[j] = max2(gg[j], __shfl_xor_sync(0xffffffffu, gg[j], 1));

    bool evencol = !(col & 1);
    int pc = col >> 1;
    if (tid >= 64 && evencol) {
#pragma unroll
        for (int j = 0; j < 4; j++)  s_pool[pc][j]     = ph[j];
#pragma unroll
        for (int j = 0; j < 16; j++) s_pool[pc][4 + j] = gg[j];
    }
    __syncthreads();
    if (tid < 64 && evencol) {
        int pp = py * 32 + pc;
        u64* pph = (u64*)&d_phi[((size_t)b * MDIM + pp) * CT];
#pragma unroll
        for (int j = 0; j < 4; j++)  pph[j] = max2(ph[j], s_pool[pc][j]);
#pragma unroll
        for (int j = 0; j < 16; j++) {
            float2 v = unpack2(max2(gg[j], s_pool[pc][4 + j]));
            d_gbuf[((size_t)b * CG + 2 * j)     * MDIM + pp] = v.x;
            d_gbuf[((size_t)b * CG + 2 * j + 1) * MDIM + pp] = v.y;
        }
    }
}

// ---------------------------------------------------------------------------
// Kernel B: mma.sync (bf16 HMMA) fused attention, 2 CTAs/SM.
// CTA = 256 queries x all 1024 keys, 256 thr (8 warps x 32 q), grid (16,16):
// 256 CTAs on 296 slots = single wave, 4 warps/SMSP.
// Scores fp32 scalar -> bf16 A-fragments in registers (no P smem).
// G bf16 smem [32][1024], XOR-swizzled (addr ^= (row&7)<<4) -> conflict-free
// B-fragment loads with zero padding. Softmax sums via scalar FADD + shfl.
// Epilogue reuses G smem as o-buffer, then w_o GEMV + residual in-CTA.
// ---------------------------------------------------------------------------
#define PHIP   8                          // fp32 per phi row (2-way LDS conflict, acceptable)
#define GROWB  2048                       // bytes per gT row (1024 bf16, swizzled)
#define OBP    34                         // fp32 per o_buf row
#define OFF_PHI 0
#define OFF_GT  (MDIM * PHIP * 4)                 // 32768
#define OFF_WO  (OFF_GT + 32 * GROWB)             // 98304
#define SMEM_SZ (OFF_WO + CDIM * 16 * 8)          // 106496

__device__ __forceinline__ void mma16816(float* c, const uint32_t* a,
                                         uint32_t b0, uint32_t b1) {
    asm volatile(
        "mma.sync.aligned.m16n8k16.row.col.f32.bf16.bf16.f32 "
        "{%0,%1,%2,%3}, {%4,%5,%6,%7}, {%8,%9}, {%0,%1,%2,%3};"
        : "+f"(c[0]), "+f"(c[1]), "+f"(c[2]), "+f"(c[3])
        : "r"(a[0]), "r"(a[1]), "r"(a[2]), "r"(a[3]), "r"(b0), "r"(b1));
}

__global__ __launch_bounds__(256, 2) void attn_mma_kernel(
    const float* __restrict__ x,
    const float* __restrict__ wo,
    const float* __restrict__ gamma,
    float* __restrict__ out)
{
    extern __shared__ __align__(16) char smem[];
    float* s_phi = (float*)(smem + OFF_PHI);
    char*  s_gt  = smem + OFF_GT;
    u64*   s_wo2 = (u64*)(smem + OFF_WO);

    int tid  = threadIdx.x;
    int lane = tid & 31, wid = tid >> 5;
    int qt   = blockIdx.x, b = blockIdx.y;

    // --- fills ---
    {   // phi: contiguous copy (rows are exactly 8 floats)
        const float4* src = (const float4*)(d_phi + (size_t)b * MDIM * CT);
        float4* dst = (float4*)s_phi;
        for (int i = tid; i < MDIM * CT / 4; i += 256) dst[i] = src[i];
    }
    for (int i = tid; i < 32 * 128; i += 256) {   // gT: bf16, swizzled
        int r = i >> 7, seg = i & 127;
        const float4* gs = (const float4*)(d_gbuf + ((size_t)b * CG + r) * MDIM + seg * 8);
        float4 A = gs[0], C = gs[1];
        __nv_bfloat162 h0 = __floats2bfloat162_rn(A.x, A.y);
        __nv_bfloat162 h1 = __floats2bfloat162_rn(A.z, A.w);
        __nv_bfloat162 h2 = __floats2bfloat162_rn(C.x, C.y);
        __nv_bfloat162 h3 = __floats2bfloat162_rn(C.z, C.w);
        uint4 w = make_uint4(*(uint32_t*)&h0, *(uint32_t*)&h1,
                             *(uint32_t*)&h2, *(uint32_t*)&h3);
        *(uint4*)(s_gt + r * GROWB + ((seg * 16) ^ ((r & 7) << 4))) = w;
    }
    for (int i = tid; i < CDIM * 16; i += 256) {
        int c = i >> 4, j = i & 15;
        s_wo2[i] = pack2(wo[c * CG + 2 * j], wo[c * CG + 2 * j + 1]);
    }
    __syncthreads();

    // --- theta in registers (4 rows x 8 floats, scaled by log2e) ---
    int r  = lane >> 2;
    int cc = lane & 3;
    int qw = qt * 256 + wid * 32;
    u64 th[4][4];
#pragma unroll
    for (int i = 0; i < 4; i++) {
        const float4* tp = (const float4*)(d_theta + ((size_t)b * HWDIM + qw + r + i * 8) * CT);
        float4 t0 = tp[0], t1 = tp[1];
        th[i][0] = pack2(t0.x * LOG2E, t0.y * LOG2E);
        th[i][1] = pack2(t0.z * LOG2E, t0.w * LOG2E);
        th[i][2] = pack2(t1.x * LOG2E, t1.y * LOG2E);
        th[i][3] = pack2(t1.z * LOG2E, t1.w * LOG2E);
    }
    const u64 s_init = pack2(-12.0f * LOG2E, 0.0f);   // uniform shift, cancels

    float acc[2][4][4];
#pragma unroll
    for (int t = 0; t < 2; t++)
#pragma unroll
        for (int nc = 0; nc < 4; nc++)
#pragma unroll
            for (int j = 0; j < 4; j++) acc[t][nc][j] = 0.0f;
    float sm[4] = {0.f, 0.f, 0.f, 0.f};

    // --- main loop: 64 chunks of 16 keys ---
    for (int k0 = 0; k0 < MDIM; k0 += 16) {
        int kc = k0 + 2 * cc;
        // phi rows kc, kc+1, kc+8, kc+9
        u64 ph[4][4];
#pragma unroll
        for (int kk = 0; kk < 4; kk++) {
            int krow = kc + (kk & 1) + (kk >> 1) * 8;
            const float4* pp = (const float4*)(s_phi + krow * PHIP);
            float4 p0 = pp[0], p1 = pp[1];
            ph[kk][0] = pack2(p0.x, p0.y); ph[kk][1] = pack2(p0.z, p0.w);
            ph[kk][2] = pack2(p1.x, p1.y); ph[kk][3] = pack2(p1.z, p1.w);
        }
        // 16 scores (4 theta rows x 4 keys) fp32, then exp; sums via FADD
        float e[4][4];
#pragma unroll
        for (int i = 0; i < 4; i++) {
#pragma unroll
            for (int kk = 0; kk < 4; kk++) {
                u64 s = ffma2(th[i][0], ph[kk][0], s_init);
                s = ffma2(th[i][1], ph[kk][1], s);
                s = ffma2(th[i][2], ph[kk][2], s);
                s = ffma2(th[i][3], ph[kk][3], s);
                float2 v = unpack2(s);
                e[i][kk] = ex2f(v.x + v.y);
            }
            sm[i] += (e[i][0] + e[i][1]) + (e[i][2] + e[i][3]);
        }
        // A fragments (bf16x2): m-tile t uses theta rows 2t, 2t+1
        uint32_t a[2][4];
#pragma unroll
        for (int t = 0; t < 2; t++) {
            a[t][0] = cvt2(e[2 * t][0],     e[2 * t][1]);
            a[t][1] = cvt2(e[2 * t + 1][0], e[2 * t + 1][1]);
            a[t][2] = cvt2(e[2 * t][2],     e[2 * t][3]);
            a[t][3] = cvt2(e[2 * t + 1][2], e[2 * t + 1][3]);
        }
        // B fragments (swizzled, conflict-free) + MMA
        uint32_t koff = (uint32_t)(k0 * 2 + 4 * cc);
        uint32_t sw   = (uint32_t)(r << 4);
#pragma unroll
        for (int nc = 0; nc < 4; nc++) {
            const char* brow = s_gt + (nc * 8 + r) * GROWB;
            uint32_t b0 = *(const uint32_t*)(brow + (koff ^ sw));
            uint32_t b1 = *(const uint32_t*)(brow + ((koff + 16) ^ sw));
            mma16816(acc[0][nc], a[0], b0, b1);
            mma16816(acc[1][nc], a[1], b0, b1);
        }
    }

    // --- reduce softmax sums across the 4 lanes of each row group ---
#pragma unroll
    for (int i = 0; i < 4; i++) {
        sm[i] += __shfl_xor_sync(0xffffffffu, sm[i], 1);
        sm[i] += __shfl_xor_sync(0xffffffffu, sm[i], 2);
    }

    // --- epilogue: normalize, stage o, GEMV, residual ---
    __syncthreads();                     // gT no longer needed
    float* o_buf = (float*)(smem + OFF_GT);
#pragma unroll
    for (int t = 0; t < 2; t++) {
        float inv0 = 1.0f / sm[2 * t];
        float inv1 = 1.0f / sm[2 * t + 1];
        int q0 = wid * 32 + 16 * t + r;
        int q1 = q0 + 8;
#pragma unroll
        for (int nc = 0; nc < 4; nc++) {
            int col = nc * 8 + 2 * cc;
            *(float2*)(o_buf + q0 * OBP + col) =
                make_float2(acc[t][nc][0] * inv0, acc[t][nc][1] * inv0);
            *(float2*)(o_buf + q1 * OBP + col) =
                make_float2(acc[t][nc][2] * inv1, acc[t][nc][3] * inv1);
        }
    }
    __syncthreads();

    u64 o2[16];
#pragma unroll
    for (int j = 0; j < 16; j++) {
        float2 v = *(float2*)(o_buf + tid * OBP + 2 * j);
        o2[j] = pack2(v.x, v.y);
    }
    float gm = *gamma;
    int n = qt * 256 + tid;
    const float* xb = x   + (size_t)b * CDIM * HWDIM + n;
    float*       ob = out + (size_t)b * CDIM * HWDIM + n;
#pragma unroll 4
    for (int c = 0; c < CDIM; c++) {
        const ulonglong2* wr = (const ulonglong2*)(s_wo2 + c * 16);
        u64 v2 = 0ull;
#pragma unroll
        for (int j = 0; j < 8; j++) {
            ulonglong2 w = wr[j];
            v2 = ffma2(w.x, o2[2 * j],     v2);
            v2 = ffma2(w.y, o2[2 * j + 1], v2);
        }
        float2 v = unpack2(v2);
        ob[(size_t)c * HWDIM] = fmaf(gm, v.x + v.y, xb[(size_t)c * HWDIM]);
    }
}

// ---------------------------------------------------------------------------
extern "C" void kernel_launch(void* const* d_in, const int* in_sizes, int n_in,
                              void* d_out, int out_size)
{
    const float* x  = (const float*)d_in[0];
    const float* wt = (const float*)d_in[1];
    const float* wp = (const float*)d_in[2];
    const float* wg = (const float*)d_in[3];
    const float* wo = (const float*)d_in[4];
    const float* gm = (const float*)d_in[5];
    float* out = (float*)d_out;

    proj_kernel<<<dim3(32, BATCH), 128>>>(x, wt, wp, wg);

    cudaFuncSetAttribute(attn_mma_kernel, cudaFuncAttributeMaxDynamicSharedMemorySize, SMEM_SZ);
    attn_mma_kernel<<<dim3(HWDIM / 256, BATCH), 256, SMEM_SZ>>>(x, wo, gm, out);
}

// round 16
// speedup vs baseline: 2.8075x; 1.3733x over previous
#include <cuda_runtime.h>
#include <cuda_bf16.h>
#include <cstdint>

// SelfAttn: B=16, C=64, H=W=64. theta/phi: 8 ch, g: 32 ch.
// phi,g maxpooled 2x2 -> M=1024 keys. HW=4096 queries.

#define BATCH 16
#define CDIM  64
#define HWDIM 4096
#define MDIM  1024
#define CT    8
#define CG    32

typedef unsigned long long u64;

__device__ __forceinline__ u64 pack2(float lo, float hi) {
    u64 r; asm("mov.b64 %0, {%1,%2};" : "=l"(r) : "f"(lo), "f"(hi)); return r;
}
__device__ __forceinline__ float2 unpack2(u64 v) {
    float2 r; asm("mov.b64 {%0,%1}, %2;" : "=f"(r.x), "=f"(r.y) : "l"(v)); return r;
}
__device__ __forceinline__ u64 ffma2(u64 a, u64 b, u64 c) {
    u64 d; asm("fma.rn.f32x2 %0, %1, %2, %3;" : "=l"(d) : "l"(a), "l"(b), "l"(c)); return d;
}
__device__ __forceinline__ float ex2f(float x) {
    float r; asm("ex2.approx.ftz.f32 %0, %1;" : "=f"(r) : "f"(x)); return r;
}
__device__ __forceinline__ u64 max2(u64 a, u64 b) {
    float2 x = unpack2(a), y = unpack2(b);
    return pack2(fmaxf(x.x, y.x), fmaxf(x.y, y.y));
}
// bf16x2 pack: lower half = lo, upper half = hi
__device__ __forceinline__ uint32_t cvt2(float lo, float hi) {
    uint32_t r; asm("cvt.rn.bf16x2.f32 %0, %1, %2;" : "=r"(r) : "f"(hi), "f"(lo)); return r;
}
__device__ __forceinline__ uint32_t tf32c(float x) {
    uint32_t r; asm("cvt.rna.tf32.f32 %0, %1;" : "=r"(r) : "f"(x)); return r;
}

#define LOG2E 1.4426950408889634f

// Scratch (allocation-free rule: __device__ globals)
__device__ float d_theta[BATCH * HWDIM * CT];   // [b][n][8]
__device__ float d_phi  [BATCH * MDIM  * CT];   // [b][m][8]
__device__ float d_gbuf [BATCH * CG * MDIM];    // TRANSPOSED: [b][ch][m]

// ---------------------------------------------------------------------------
// Kernel A: 1x1 projections + fused 2x2 maxpool for phi/g. (unchanged)
// ---------------------------------------------------------------------------
__global__ __launch_bounds__(128) void proj_kernel(
    const float* __restrict__ x,
    const float* __restrict__ wt,
    const float* __restrict__ wp,
    const float* __restrict__ wg)
{
    __shared__ __align__(16) u64 s_wt2[CDIM * 4];
    __shared__ __align__(16) u64 s_wp2[CDIM * 4];
    __shared__ __align__(16) u64 s_wg2[CDIM * 16];
    __shared__ __align__(16) u64 s_pool[32][20];
    int tid = threadIdx.x;
    for (int i = tid; i < CDIM * 4; i += 128) {
        int c = i >> 2, j = i & 3;
        s_wt2[i] = pack2(wt[(2 * j) * CDIM + c], wt[(2 * j + 1) * CDIM + c]);
        s_wp2[i] = pack2(wp[(2 * j) * CDIM + c], wp[(2 * j + 1) * CDIM + c]);
    }
    for (int i = tid; i < CDIM * 16; i += 128) {
        int c = i >> 4, j = i & 15;
        s_wg2[i] = pack2(wg[(2 * j) * CDIM + c], wg[(2 * j + 1) * CDIM + c]);
    }
    __syncthreads();

    int b   = blockIdx.y;
    int py  = blockIdx.x;
    int row = 2 * py + (tid >> 6);
    int col = tid & 63;
    int pix = row * 64 + col;
    const float* xb = x + (size_t)b * CDIM * HWDIM;

    u64 th[4], ph[4], gg[16];
#pragma unroll
    for (int j = 0; j < 4; j++) { th[j] = 0ull; ph[j] = 0ull; }
#pragma unroll
    for (int j = 0; j < 16; j++) gg[j] = 0ull;

#pragma unroll 8
    for (int c = 0; c < CDIM; c++) {
        float a = xb[(size_t)c * HWDIM + pix];
        u64 x2 = pack2(a, a);
        const ulonglong2* wtp = (const ulonglong2*)(s_wt2 + c * 4);
        const ulonglong2* wpp = (const ulonglong2*)(s_wp2 + c * 4);
        const ulonglong2* wgp = (const ulonglong2*)(s_wg2 + c * 16);
#pragma unroll
        for (int jj = 0; jj < 2; jj++) {
            ulonglong2 w = wtp[jj];
            th[2 * jj]     = ffma2(w.x, x2, th[2 * jj]);
            th[2 * jj + 1] = ffma2(w.y, x2, th[2 * jj + 1]);
            ulonglong2 v = wpp[jj];
            ph[2 * jj]     = ffma2(v.x, x2, ph[2 * jj]);
            ph[2 * jj + 1] = ffma2(v.y, x2, ph[2 * jj + 1]);
        }
#pragma unroll
        for (int jj = 0; jj < 8; jj++) {
            ulonglong2 w = wgp[jj];
            gg[2 * jj]     = ffma2(w.x, x2, gg[2 * jj]);
            gg[2 * jj + 1] = ffma2(w.y, x2, gg[2 * jj + 1]);
        }
    }

    {
        ulonglong2* tp = (ulonglong2*)&d_theta[((size_t)b * HWDIM + pix) * CT];
        tp[0] = make_ulonglong2(th[0], th[1]);
        tp[1] = make_ulonglong2(th[2], th[3]);
    }

#pragma unroll
    for (int j = 0; j < 4; j++)
        ph[j] = max2(ph[j], __shfl_xor_sync(0xffffffffu, ph[j], 1));
#pragma unroll
    for (int j = 0; j < 16; j++)
        gg[j] = max2(gg[j], __shfl_xor_sync(0xffffffffu, gg[j], 1));

    bool evencol = !(col & 1);
    int pc = col >> 1;
    if (tid >= 64 && evencol) {
#pragma unroll
        for (int j = 0; j < 4; j++)  s_pool[pc][j]     = ph[j];
#pragma unroll
        for (int j = 0; j < 16; j++) s_pool[pc][4 + j] = gg[j];
    }
    __syncthreads();
    if (tid < 64 && evencol) {
        int pp = py * 32 + pc;
        u64* pph = (u64*)&d_phi[((size_t)b * MDIM + pp) * CT];
#pragma unroll
        for (int j = 0; j < 4; j++)  pph[j] = max2(ph[j], s_pool[pc][j]);
#pragma unroll
        for (int j = 0; j < 16; j++) {
            float2 v = unpack2(max2(gg[j], s_pool[pc][4 + j]));
            d_gbuf[((size_t)b * CG + 2 * j)     * MDIM + pp] = v.x;
            d_gbuf[((size_t)b * CG + 2 * j + 1) * MDIM + pp] = v.y;
        }
    }
}

// ---------------------------------------------------------------------------
// Kernel B: full tensor-core attention.
// Scores: mma.m16n8k8 tf32 (theta regs x phiT smem frags) -> C frags map
// 1:1 onto the bf16 value-MMA A frags after exp+cvt. No shift (range safe).
// G bf16 smem [32][1024] XOR-swizzled; phiT tf32 [8][1032] conflict-free.
// Per-chunk warp work: 4 LDS + 4 MMA + 16 ex2 + 16 FADD + 8 cvt + 8 LDS +
// 8 MMA => MUFU(exp)-bound. 2 CTAs/SM, single wave.
// ---------------------------------------------------------------------------
#define PHIP   1032                       // tf32 words per phiT row
#define GROWB  2048                       // bytes per gT row
#define OBP    34                         // fp32 per o_buf row
#define OFF_PHIT 0
#define OFF_GT  (8 * PHIP * 4)                    // 33024
#define OFF_WO  (OFF_GT + 32 * GROWB)             // 98560
#define SMEM_SZ (OFF_WO + CDIM * 16 * 8)          // 106752

__device__ __forceinline__ void mma16816(float* c, const uint32_t* a,
                                         uint32_t b0, uint32_t b1) {
    asm volatile(
        "mma.sync.aligned.m16n8k16.row.col.f32.bf16.bf16.f32 "
        "{%0,%1,%2,%3}, {%4,%5,%6,%7}, {%8,%9}, {%0,%1,%2,%3};"
        : "+f"(c[0]), "+f"(c[1]), "+f"(c[2]), "+f"(c[3])
        : "r"(a[0]), "r"(a[1]), "r"(a[2]), "r"(a[3]), "r"(b0), "r"(b1));
}
__device__ __forceinline__ void mma1688tf(float* d, const uint32_t* a,
                                          uint32_t b0, uint32_t b1) {
    float z = 0.0f;
    asm volatile(
        "mma.sync.aligned.m16n8k8.row.col.f32.tf32.tf32.f32 "
        "{%0,%1,%2,%3}, {%4,%5,%6,%7}, {%8,%9}, {%10,%10,%10,%10};"
        : "=f"(d[0]), "=f"(d[1]), "=f"(d[2]), "=f"(d[3])
        : "r"(a[0]), "r"(a[1]), "r"(a[2]), "r"(a[3]), "r"(b0), "r"(b1), "f"(z));
}

__global__ __launch_bounds__(256, 2) void attn_mma_kernel(
    const float* __restrict__ x,
    const float* __restrict__ wo,
    const float* __restrict__ gamma,
    float* __restrict__ out)
{
    extern __shared__ __align__(16) char smem[];
    uint32_t* s_phiT = (uint32_t*)(smem + OFF_PHIT);   // [8][1032] tf32
    char*     s_gt   = smem + OFF_GT;
    u64*      s_wo2  = (u64*)(smem + OFF_WO);

    int tid  = threadIdx.x;
    int lane = tid & 31, wid = tid >> 5;
    int qt   = blockIdx.x, b = blockIdx.y;

    // --- fills ---
    for (int i = tid; i < MDIM; i += 256) {    // phiT: transpose + tf32 cvt
        const float4* pp = (const float4*)(d_phi + ((size_t)b * MDIM + i) * CT);
        float4 p0 = pp[0], p1 = pp[1];
        s_phiT[0 * PHIP + i] = tf32c(p0.x);
        s_phiT[1 * PHIP + i] = tf32c(p0.y);
        s_phiT[2 * PHIP + i] = tf32c(p0.z);
        s_phiT[3 * PHIP + i] = tf32c(p0.w);
        s_phiT[4 * PHIP + i] = tf32c(p1.x);
        s_phiT[5 * PHIP + i] = tf32c(p1.y);
        s_phiT[6 * PHIP + i] = tf32c(p1.z);
        s_phiT[7 * PHIP + i] = tf32c(p1.w);
    }
    for (int i = tid; i < 32 * 128; i += 256) {   // gT: bf16, swizzled
        int r = i >> 7, seg = i & 127;
        const float4* gs = (const float4*)(d_gbuf + ((size_t)b * CG + r) * MDIM + seg * 8);
        float4 A = gs[0], C = gs[1];
        __nv_bfloat162 h0 = __floats2bfloat162_rn(A.x, A.y);
        __nv_bfloat162 h1 = __floats2bfloat162_rn(A.z, A.w);
        __nv_bfloat162 h2 = __floats2bfloat162_rn(C.x, C.y);
        __nv_bfloat162 h3 = __floats2bfloat162_rn(C.z, C.w);
        uint4 w = make_uint4(*(uint32_t*)&h0, *(uint32_t*)&h1,
                             *(uint32_t*)&h2, *(uint32_t*)&h3);
        *(uint4*)(s_gt + r * GROWB + ((seg * 16) ^ ((r & 7) << 4))) = w;
    }
    for (int i = tid; i < CDIM * 16; i += 256) {
        int c = i >> 4, j = i & 15;
        s_wo2[i] = pack2(wo[c * CG + 2 * j], wo[c * CG + 2 * j + 1]);
    }
    __syncthreads();

    // --- theta A-fragments (tf32, scaled by log2e), held all loop ---
    int r  = lane >> 2;          // groupID (row)
    int cc = lane & 3;           // threadID in group
    uint32_t th[2][4];
#pragma unroll
    for (int t = 0; t < 2; t++) {
        int qb = qt * 256 + wid * 32 + 16 * t;
        const float* tb = d_theta + ((size_t)b * HWDIM + qb) * CT;
        th[t][0] = tf32c(tb[(size_t)r * CT + cc] * LOG2E);
        th[t][1] = tf32c(tb[(size_t)(r + 8) * CT + cc] * LOG2E);
        th[t][2] = tf32c(tb[(size_t)r * CT + cc + 4] * LOG2E);
        th[t][3] = tf32c(tb[(size_t)(r + 8) * CT + cc + 4] * LOG2E);
    }

    float acc[2][4][4];
#pragma unroll
    for (int t = 0; t < 2; t++)
#pragma unroll
        for (int nc = 0; nc < 4; nc++)
#pragma unroll
            for (int j = 0; j < 4; j++) acc[t][nc][j] = 0.0f;
    float sm[4] = {0.f, 0.f, 0.f, 0.f};

    // --- main loop: 64 chunks of 16 keys ---
    for (int k0 = 0; k0 < MDIM; k0 += 16) {
        // phi B-fragments (conflict-free: bank = 8cc+gid)
        uint32_t pb[4];
        pb[0] = s_phiT[cc * PHIP + k0 + r];
        pb[1] = s_phiT[(cc + 4) * PHIP + k0 + r];
        pb[2] = s_phiT[cc * PHIP + k0 + 8 + r];
        pb[3] = s_phiT[(cc + 4) * PHIP + k0 + 8 + r];

        // scores: 2 M-tiles x 2 N-tiles of m16n8k8 tf32
        float c[2][2][4];
#pragma unroll
        for (int t = 0; t < 2; t++) {
            mma1688tf(c[t][0], th[t], pb[0], pb[1]);
            mma1688tf(c[t][1], th[t], pb[2], pb[3]);
        }
        // exp + sums + pack into value-MMA A fragments
        uint32_t a[2][4];
#pragma unroll
        for (int t = 0; t < 2; t++) {
            float e00 = ex2f(c[t][0][0]), e01 = ex2f(c[t][0][1]);
            float e02 = ex2f(c[t][0][2]), e03 = ex2f(c[t][0][3]);
            float e10 = ex2f(c[t][1][0]), e11 = ex2f(c[t][1][1]);
            float e12 = ex2f(c[t][1][2]), e13 = ex2f(c[t][1][3]);
            sm[2 * t]     += (e00 + e01) + (e10 + e11);
            sm[2 * t + 1] += (e02 + e03) + (e12 + e13);
            a[t][0] = cvt2(e00, e01);
            a[t][1] = cvt2(e02, e03);
            a[t][2] = cvt2(e10, e11);
            a[t][3] = cvt2(e12, e13);
        }
        // value MMAs (bf16), B from swizzled gT
        uint32_t koff = (uint32_t)(k0 * 2 + 4 * cc);
        uint32_t sw   = (uint32_t)(r << 4);
#pragma unroll
        for (int nc = 0; nc < 4; nc++) {
            const char* brow = s_gt + (nc * 8 + r) * GROWB;
            uint32_t b0 = *(const uint32_t*)(brow + (koff ^ sw));
            uint32_t b1 = *(const uint32_t*)(brow + ((koff + 16) ^ sw));
            mma16816(acc[0][nc], a[0], b0, b1);
            mma16816(acc[1][nc], a[1], b0, b1);
        }
    }

    // --- reduce softmax sums across the 4 lanes of each row group ---
#pragma unroll
    for (int i = 0; i < 4; i++) {
        sm[i] += __shfl_xor_sync(0xffffffffu, sm[i], 1);
        sm[i] += __shfl_xor_sync(0xffffffffu, sm[i], 2);
    }

    // --- epilogue: normalize, stage o, GEMV, residual ---
    __syncthreads();                     // gT no longer needed
    float* o_buf = (float*)(smem + OFF_GT);
#pragma unroll
    for (int t = 0; t < 2; t++) {
        float inv0 = 1.0f / sm[2 * t];
        float inv1 = 1.0f / sm[2 * t + 1];
        int q0 = wid * 32 + 16 * t + r;
        int q1 = q0 + 8;
#pragma unroll
        for (int nc = 0; nc < 4; nc++) {
            int col = nc * 8 + 2 * cc;
            *(float2*)(o_buf + q0 * OBP + col) =
                make_float2(acc[t][nc][0] * inv0, acc[t][nc][1] * inv0);
            *(float2*)(o_buf + q1 * OBP + col) =
                make_float2(acc[t][nc][2] * inv1, acc[t][nc][3] * inv1);
        }
    }
    __syncthreads();

    u64 o2[16];
#pragma unroll
    for (int j = 0; j < 16; j++) {
        float2 v = *(float2*)(o_buf + tid * OBP + 2 * j);
        o2[j] = pack2(v.x, v.y);
    }
    float gm = *gamma;
    int n = qt * 256 + tid;
    const float* xb = x   + (size_t)b * CDIM * HWDIM + n;
    float*       ob = out + (size_t)b * CDIM * HWDIM + n;
#pragma unroll 4
    for (int c = 0; c < CDIM; c++) {
        const ulonglong2* wr = (const ulonglong2*)(s_wo2 + c * 16);
        u64 v2 = 0ull;
#pragma unroll
        for (int j = 0; j < 8; j++) {
            ulonglong2 w = wr[j];
            v2 = ffma2(w.x, o2[2 * j],     v2);
            v2 = ffma2(w.y, o2[2 * j + 1], v2);
        }
        float2 v = unpack2(v2);
        ob[(size_t)c * HWDIM] = fmaf(gm, v.x + v.y, xb[(size_t)c * HWDIM]);
    }
}

// ---------------------------------------------------------------------------
extern "C" void kernel_launch(void* const* d_in, const int* in_sizes, int n_in,
                              void* d_out, int out_size)
{
    const float* x  = (const float*)d_in[0];
    const float* wt = (const float*)d_in[1];
    const float* wp = (const float*)d_in[2];
    const float* wg = (const float*)d_in[3];
    const float* wo = (const float*)d_in[4];
    const float* gm = (const float*)d_in[5];
    float* out = (float*)d_out;

    proj_kernel<<<dim3(32, BATCH), 128>>>(x, wt, wp, wg);

    cudaFuncSetAttribute(attn_mma_kernel, cudaFuncAttributeMaxDynamicSharedMemorySize, SMEM_SZ);
    attn_mma_kernel<<<dim3(HWDIM / 256, BATCH), 256, SMEM_SZ>>>(x, wo, gm, out);
}

// round 17
// speedup vs baseline: 2.8516x; 1.0157x over previous
#include <cuda_runtime.h>
#include <cuda_bf16.h>
#include <cstdint>

// SelfAttn: B=16, C=64, H=W=64. theta/phi: 8 ch, g: 32 ch.
// phi,g maxpooled 2x2 -> M=1024 keys. HW=4096 queries.

#define BATCH 16
#define CDIM  64
#define HWDIM 4096
#define MDIM  1024
#define CT    8
#define CG    32

typedef unsigned long long u64;

__device__ __forceinline__ u64 pack2(float lo, float hi) {
    u64 r; asm("mov.b64 %0, {%1,%2};" : "=l"(r) : "f"(lo), "f"(hi)); return r;
}
__device__ __forceinline__ float2 unpack2(u64 v) {
    float2 r; asm("mov.b64 {%0,%1}, %2;" : "=f"(r.x), "=f"(r.y) : "l"(v)); return r;
}
__device__ __forceinline__ u64 ffma2(u64 a, u64 b, u64 c) {
    u64 d; asm("fma.rn.f32x2 %0, %1, %2, %3;" : "=l"(d) : "l"(a), "l"(b), "l"(c)); return d;
}
__device__ __forceinline__ float ex2f(float x) {
    float r; asm("ex2.approx.ftz.f32 %0, %1;" : "=f"(r) : "f"(x)); return r;
}
__device__ __forceinline__ u64 max2(u64 a, u64 b) {
    float2 x = unpack2(a), y = unpack2(b);
    return pack2(fmaxf(x.x, y.x), fmaxf(x.y, y.y));
}
// bf16x2 pack: lower half = lo, upper half = hi
__device__ __forceinline__ uint32_t cvt2(float lo, float hi) {
    uint32_t r; asm("cvt.rn.bf16x2.f32 %0, %1, %2;" : "=r"(r) : "f"(hi), "f"(lo)); return r;
}
__device__ __forceinline__ uint32_t tf32c(float x) {
    uint32_t r; asm("cvt.rna.tf32.f32 %0, %1;" : "=r"(r) : "f"(x)); return r;
}

#define LOG2E 1.4426950408889634f

// Scratch (allocation-free rule: __device__ globals)
__device__ float d_theta[BATCH * HWDIM * CT];   // [b][n][8]
__device__ float d_phi  [BATCH * MDIM  * CT];   // [b][m][8]
__device__ float d_gbuf [BATCH * CG * MDIM];    // TRANSPOSED: [b][ch][m]

// ---------------------------------------------------------------------------
// Kernel A: 1x1 projections + fused 2x2 maxpool for phi/g. (unchanged)
// ---------------------------------------------------------------------------
__global__ __launch_bounds__(128) void proj_kernel(
    const float* __restrict__ x,
    const float* __restrict__ wt,
    const float* __restrict__ wp,
    const float* __restrict__ wg)
{
    __shared__ __align__(16) u64 s_wt2[CDIM * 4];
    __shared__ __align__(16) u64 s_wp2[CDIM * 4];
    __shared__ __align__(16) u64 s_wg2[CDIM * 16];
    __shared__ __align__(16) u64 s_pool[32][20];
    int tid = threadIdx.x;
    for (int i = tid; i < CDIM * 4; i += 128) {
        int c = i >> 2, j = i & 3;
        s_wt2[i] = pack2(wt[(2 * j) * CDIM + c], wt[(2 * j + 1) * CDIM + c]);
        s_wp2[i] = pack2(wp[(2 * j) * CDIM + c], wp[(2 * j + 1) * CDIM + c]);
    }
    for (int i = tid; i < CDIM * 16; i += 128) {
        int c = i >> 4, j = i & 15;
        s_wg2[i] = pack2(wg[(2 * j) * CDIM + c], wg[(2 * j + 1) * CDIM + c]);
    }
    __syncthreads();

    int b   = blockIdx.y;
    int py  = blockIdx.x;
    int row = 2 * py + (tid >> 6);
    int col = tid & 63;
    int pix = row * 64 + col;
    const float* xb = x + (size_t)b * CDIM * HWDIM;

    u64 th[4], ph[4], gg[16];
#pragma unroll
    for (int j = 0; j < 4; j++) { th[j] = 0ull; ph[j] = 0ull; }
#pragma unroll
    for (int j = 0; j < 16; j++) gg[j] = 0ull;

#pragma unroll 8
    for (int c = 0; c < CDIM; c++) {
        float a = xb[(size_t)c * HWDIM + pix];
        u64 x2 = pack2(a, a);
        const ulonglong2* wtp = (const ulonglong2*)(s_wt2 + c * 4);
        const ulonglong2* wpp = (const ulonglong2*)(s_wp2 + c * 4);
        const ulonglong2* wgp = (const ulonglong2*)(s_wg2 + c * 16);
#pragma unroll
        for (int jj = 0; jj < 2; jj++) {
            ulonglong2 w = wtp[jj];
            th[2 * jj]     = ffma2(w.x, x2, th[2 * jj]);
            th[2 * jj + 1] = ffma2(w.y, x2, th[2 * jj + 1]);
            ulonglong2 v = wpp[jj];
            ph[2 * jj]     = ffma2(v.x, x2, ph[2 * jj]);
            ph[2 * jj + 1] = ffma2(v.y, x2, ph[2 * jj + 1]);
        }
#pragma unroll
        for (int jj = 0; jj < 8; jj++) {
            ulonglong2 w = wgp[jj];
            gg[2 * jj]     = ffma2(w.x, x2, gg[2 * jj]);
            gg[2 * jj + 1] = ffma2(w.y, x2, gg[2 * jj + 1]);
        }
    }

    {
        ulonglong2* tp = (ulonglong2*)&d_theta[((size_t)b * HWDIM + pix) * CT];
        tp[0] = make_ulonglong2(th[0], th[1]);
        tp[1] = make_ulonglong2(th[2], th[3]);
    }

#pragma unroll
    for (int j = 0; j < 4; j++)
        ph[j] = max2(ph[j], __shfl_xor_sync(0xffffffffu, ph[j], 1));
#pragma unroll
    for (int j = 0; j < 16; j++)
        gg[j] = max2(gg[j], __shfl_xor_sync(0xffffffffu, gg[j], 1));

    bool evencol = !(col & 1);
    int pc = col >> 1;
    if (tid >= 64 && evencol) {
#pragma unroll
        for (int j = 0; j < 4; j++)  s_pool[pc][j]     = ph[j];
#pragma unroll
        for (int j = 0; j < 16; j++) s_pool[pc][4 + j] = gg[j];
    }
    __syncthreads();
    if (tid < 64 && evencol) {
        int pp = py * 32 + pc;
        u64* pph = (u64*)&d_phi[((size_t)b * MDIM + pp) * CT];
#pragma unroll
        for (int j = 0; j < 4; j++)  pph[j] = max2(ph[j], s_pool[pc][j]);
#pragma unroll
        for (int j = 0; j < 16; j++) {
            float2 v = unpack2(max2(gg[j], s_pool[pc][4 + j]));
            d_gbuf[((size_t)b * CG + 2 * j)     * MDIM + pp] = v.x;
            d_gbuf[((size_t)b * CG + 2 * j + 1) * MDIM + pp] = v.y;
        }
    }
}

// ---------------------------------------------------------------------------
// Kernel B: full tensor-core attention, software-pipelined.
// Scores: mma.m16n8k8 tf32; values: mma.m16n8k16 bf16. All next-chunk LDS
// operands (phiT + gT fragments) prefetched into registers -> LDS latency
// off the critical chain; chain is MMA -> ex2 -> cvt -> MMA only.
// 2 CTAs/SM, single wave (256 CTAs resident).
// ---------------------------------------------------------------------------
#define PHIP   1032                       // tf32 words per phiT row
#define GROWB  2048                       // bytes per gT row
#define OBP    34                         // fp32 per o_buf row
#define OFF_PHIT 0
#define OFF_GT  (8 * PHIP * 4)                    // 33024
#define OFF_WO  (OFF_GT + 32 * GROWB)             // 98560
#define SMEM_SZ (OFF_WO + CDIM * 16 * 8)          // 106752

__device__ __forceinline__ void mma16816(float* c, const uint32_t* a,
                                         uint32_t b0, uint32_t b1) {
    asm volatile(
        "mma.sync.aligned.m16n8k16.row.col.f32.bf16.bf16.f32 "
        "{%0,%1,%2,%3}, {%4,%5,%6,%7}, {%8,%9}, {%0,%1,%2,%3};"
        : "+f"(c[0]), "+f"(c[1]), "+f"(c[2]), "+f"(c[3])
        : "r"(a[0]), "r"(a[1]), "r"(a[2]), "r"(a[3]), "r"(b0), "r"(b1));
}
__device__ __forceinline__ void mma1688tf(float* d, const uint32_t* a,
                                          uint32_t b0, uint32_t b1) {
    float z = 0.0f;
    asm volatile(
        "mma.sync.aligned.m16n8k8.row.col.f32.tf32.tf32.f32 "
        "{%0,%1,%2,%3}, {%4,%5,%6,%7}, {%8,%9}, {%10,%10,%10,%10};"
        : "=f"(d[0]), "=f"(d[1]), "=f"(d[2]), "=f"(d[3])
        : "r"(a[0]), "r"(a[1]), "r"(a[2]), "r"(a[3]), "r"(b0), "r"(b1), "f"(z));
}

__global__ __launch_bounds__(256, 2) void attn_mma_kernel(
    const float* __restrict__ x,
    const float* __restrict__ wo,
    const float* __restrict__ gamma,
    float* __restrict__ out)
{
    extern __shared__ __align__(16) char smem[];
    uint32_t* s_phiT = (uint32_t*)(smem + OFF_PHIT);   // [8][1032] tf32
    char*     s_gt   = smem + OFF_GT;
    u64*      s_wo2  = (u64*)(smem + OFF_WO);

    int tid  = threadIdx.x;
    int lane = tid & 31, wid = tid >> 5;
    int qt   = blockIdx.x, b = blockIdx.y;

    // --- fills ---
    for (int i = tid; i < MDIM; i += 256) {    // phiT: transpose + tf32 cvt
        const float4* pp = (const float4*)(d_phi + ((size_t)b * MDIM + i) * CT);
        float4 p0 = pp[0], p1 = pp[1];
        s_phiT[0 * PHIP + i] = tf32c(p0.x);
        s_phiT[1 * PHIP + i] = tf32c(p0.y);
        s_phiT[2 * PHIP + i] = tf32c(p0.z);
        s_phiT[3 * PHIP + i] = tf32c(p0.w);
        s_phiT[4 * PHIP + i] = tf32c(p1.x);
        s_phiT[5 * PHIP + i] = tf32c(p1.y);
        s_phiT[6 * PHIP + i] = tf32c(p1.z);
        s_phiT[7 * PHIP + i] = tf32c(p1.w);
    }
    for (int i = tid; i < 32 * 128; i += 256) {   // gT: bf16, swizzled
        int r = i >> 7, seg = i & 127;
        const float4* gs = (const float4*)(d_gbuf + ((size_t)b * CG + r) * MDIM + seg * 8);
        float4 A = gs[0], C = gs[1];
        __nv_bfloat162 h0 = __floats2bfloat162_rn(A.x, A.y);
        __nv_bfloat162 h1 = __floats2bfloat162_rn(A.z, A.w);
        __nv_bfloat162 h2 = __floats2bfloat162_rn(C.x, C.y);
        __nv_bfloat162 h3 = __floats2bfloat162_rn(C.z, C.w);
        uint4 w = make_uint4(*(uint32_t*)&h0, *(uint32_t*)&h1,
                             *(uint32_t*)&h2, *(uint32_t*)&h3);
        *(uint4*)(s_gt + r * GROWB + ((seg * 16) ^ ((r & 7) << 4))) = w;
    }
    for (int i = tid; i < CDIM * 16; i += 256) {
        int c = i >> 4, j = i & 15;
        s_wo2[i] = pack2(wo[c * CG + 2 * j], wo[c * CG + 2 * j + 1]);
    }
    __syncthreads();

    // --- theta A-fragments (tf32, scaled by log2e), held all loop ---
    int r  = lane >> 2;          // groupID (row)
    int cc = lane & 3;           // threadID in group
    uint32_t th[2][4];
#pragma unroll
    for (int t = 0; t < 2; t++) {
        int qb = qt * 256 + wid * 32 + 16 * t;
        const float* tb = d_theta + ((size_t)b * HWDIM + qb) * CT;
        th[t][0] = tf32c(tb[(size_t)r * CT + cc] * LOG2E);
        th[t][1] = tf32c(tb[(size_t)(r + 8) * CT + cc] * LOG2E);
        th[t][2] = tf32c(tb[(size_t)r * CT + cc + 4] * LOG2E);
        th[t][3] = tf32c(tb[(size_t)(r + 8) * CT + cc + 4] * LOG2E);
    }

    float acc[2][4][4];
#pragma unroll
    for (int t = 0; t < 2; t++)
#pragma unroll
        for (int nc = 0; nc < 4; nc++)
#pragma unroll
            for (int j = 0; j < 4; j++) acc[t][nc][j] = 0.0f;
    float sm[4] = {0.f, 0.f, 0.f, 0.f};

    // --- operand prefetch helpers (register-resident pipeline) ---
    const uint32_t sw = (uint32_t)(r << 4);
    uint32_t pb[4], bf[8];
    {   // preload chunk 0
        pb[0] = s_phiT[cc * PHIP + r];
        pb[1] = s_phiT[(cc + 4) * PHIP + r];
        pb[2] = s_phiT[cc * PHIP + 8 + r];
        pb[3] = s_phiT[(cc + 4) * PHIP + 8 + r];
        uint32_t koff = (uint32_t)(4 * cc);
#pragma unroll
        for (int nc = 0; nc < 4; nc++) {
            const char* brow = s_gt + (nc * 8 + r) * GROWB;
            bf[2 * nc]     = *(const uint32_t*)(brow + (koff ^ sw));
            bf[2 * nc + 1] = *(const uint32_t*)(brow + ((koff + 16) ^ sw));
        }
    }

    // --- main loop: 64 chunks of 16 keys, next-chunk operands prefetched ---
#pragma unroll 2
    for (int k0 = 0; k0 < MDIM; k0 += 16) {
        int kn = k0 + 16;
        // prefetch next chunk (unconditional; reads stay inside smem, values
        // discarded on the final iteration)
        uint32_t pbn[4], bfn[8];
        pbn[0] = s_phiT[cc * PHIP + kn + r];
        pbn[1] = s_phiT[(cc + 4) * PHIP + kn + r];
        pbn[2] = s_phiT[cc * PHIP + kn + 8 + r];
        pbn[3] = s_phiT[(cc + 4) * PHIP + kn + 8 + r];
        {
            uint32_t koff = (uint32_t)(kn * 2 + 4 * cc);
#pragma unroll
            for (int nc = 0; nc < 4; nc++) {
                const char* brow = s_gt + (nc * 8 + r) * GROWB;
                bfn[2 * nc]     = *(const uint32_t*)(brow + (koff ^ sw));
                bfn[2 * nc + 1] = *(const uint32_t*)(brow + ((koff + 16) ^ sw));
            }
        }

        // scores: 2 M-tiles x 2 N-tiles of m16n8k8 tf32
        float c[2][2][4];
#pragma unroll
        for (int t = 0; t < 2; t++) {
            mma1688tf(c[t][0], th[t], pb[0], pb[1]);
            mma1688tf(c[t][1], th[t], pb[2], pb[3]);
        }
        // exp + sums + pack into value-MMA A fragments
        uint32_t a[2][4];
#pragma unroll
        for (int t = 0; t < 2; t++) {
            float e00 = ex2f(c[t][0][0]), e01 = ex2f(c[t][0][1]);
            float e02 = ex2f(c[t][0][2]), e03 = ex2f(c[t][0][3]);
            float e10 = ex2f(c[t][1][0]), e11 = ex2f(c[t][1][1]);
            float e12 = ex2f(c[t][1][2]), e13 = ex2f(c[t][1][3]);
            sm[2 * t]     += (e00 + e01) + (e10 + e11);
            sm[2 * t + 1] += (e02 + e03) + (e12 + e13);
            a[t][0] = cvt2(e00, e01);
            a[t][1] = cvt2(e02, e03);
            a[t][2] = cvt2(e10, e11);
            a[t][3] = cvt2(e12, e13);
        }
        // value MMAs (bf16), B fragments already in registers
#pragma unroll
        for (int nc = 0; nc < 4; nc++) {
            mma16816(acc[0][nc], a[0], bf[2 * nc], bf[2 * nc + 1]);
            mma16816(acc[1][nc], a[1], bf[2 * nc], bf[2 * nc + 1]);
        }
        // rotate pipeline registers
#pragma unroll
        for (int j = 0; j < 4; j++) pb[j] = pbn[j];
#pragma unroll
        for (int j = 0; j < 8; j++) bf[j] = bfn[j];
    }

    // --- reduce softmax sums across the 4 lanes of each row group ---
#pragma unroll
    for (int i = 0; i < 4; i++) {
        sm[i] += __shfl_xor_sync(0xffffffffu, sm[i], 1);
        sm[i] += __shfl_xor_sync(0xffffffffu, sm[i], 2);
    }

    // --- epilogue: normalize, stage o, GEMV, residual ---
    __syncthreads();                     // gT no longer needed
    float* o_buf = (float*)(smem + OFF_GT);
#pragma unroll
    for (int t = 0; t < 2; t++) {
        float inv0 = 1.0f / sm[2 * t];
        float inv1 = 1.0f / sm[2 * t + 1];
        int q0 = wid * 32 + 16 * t + r;
        int q1 = q0 + 8;
#pragma unroll
        for (int nc = 0; nc < 4; nc++) {
            int col = nc * 8 + 2 * cc;
            *(float2*)(o_buf + q0 * OBP + col) =
                make_float2(acc[t][nc][0] * inv0, acc[t][nc][1] * inv0);
            *(float2*)(o_buf + q1 * OBP + col) =
                make_float2(acc[t][nc][2] * inv1, acc[t][nc][3] * inv1);
        }
    }
    __syncthreads();

    u64 o2[16];
#pragma unroll
    for (int j = 0; j < 16; j++) {
        float2 v = *(float2*)(o_buf + tid * OBP + 2 * j);
        o2[j] = pack2(v.x, v.y);
    }
    float gm = *gamma;
    int n = qt * 256 + tid;
    const float* xb = x   + (size_t)b * CDIM * HWDIM + n;
    float*       ob = out + (size_t)b * CDIM * HWDIM + n;
#pragma unroll 4
    for (int c = 0; c < CDIM; c++) {
        const ulonglong2* wr = (const ulonglong2*)(s_wo2 + c * 16);
        u64 v2 = 0ull;
#pragma unroll
        for (int j = 0; j < 8; j++) {
            ulonglong2 w = wr[j];
            v2 = ffma2(w.x, o2[2 * j],     v2);
            v2 = ffma2(w.y, o2[2 * j + 1], v2);
        }
        float2 v = unpack2(v2);
        ob[(size_t)c * HWDIM] = fmaf(gm, v.x + v.y, xb[(size_t)c * HWDIM]);
    }
}

// ---------------------------------------------------------------------------
extern "C" void kernel_launch(void* const* d_in, const int* in_sizes, int n_in,
                              void* d_out, int out_size)
{
    const float* x  = (const float*)d_in[0];
    const float* wt = (const float*)d_in[1];
    const float* wp = (const float*)d_in[2];
    const float* wg = (const float*)d_in[3];
    const float* wo = (const float*)d_in[4];
    const float* gm = (const float*)d_in[5];
    float* out = (float*)d_out;

    proj_kernel<<<dim3(32, BATCH), 128>>>(x, wt, wp, wg);

    cudaFuncSetAttribute(attn_mma_kernel, cudaFuncAttributeMaxDynamicSharedMemorySize, SMEM_SZ);
    attn_mma_kernel<<<dim3(HWDIM / 256, BATCH), 256, SMEM_SZ>>>(x, wo, gm, out);
}